// round 6
// baseline (speedup 1.0000x reference)
#include <cuda_runtime.h>
#include <cuda_fp16.h>
#include <cstdint>
#include <math_constants.h>

// Problem dims (fixed per reference)
#define DM   1024      // d_model
#define DF   4096      // d_ff
#define MROWS 16384    // 4 * 4096

// ---------------------------------------------------------------------------
// Scratch (allocation-free: __device__ globals)
// ---------------------------------------------------------------------------
__device__ float  g_scores[(size_t)MROWS * DF];   // 256 MB fp32 logits
__device__ __half g_phi[(size_t)MROWS * DF];      // probs (single fp16)
__device__ __half g_xhi[(size_t)MROWS * DM];      // (xs*x) hi
__device__ __half g_xlo[(size_t)MROWS * DM];
__device__ __half g_whi[(size_t)DF * DM];         // (ws*w) hi
__device__ __half g_wlo[(size_t)DF * DM];
__device__ __half g_wthi[(size_t)DM * DF];        // W^T (raw w) [d][c], single fp16
__device__ float  g_xscale[MROWS];
__device__ float  g_wscale[DF];

// ---------------------------------------------------------------------------
// PTX helpers
// ---------------------------------------------------------------------------
__device__ __forceinline__ uint32_t smem_u32_of(const void* p) {
    uint32_t a;
    asm("{ .reg .u64 t; cvta.to.shared.u64 t, %1; cvt.u32.u64 %0, t; }" : "=r"(a) : "l"(p));
    return a;
}

__device__ __forceinline__ void cp16(uint32_t s, const void* g) {
    asm volatile("cp.async.cg.shared.global [%0], [%1], 16;" :: "r"(s), "l"(g));
}

__device__ __forceinline__ void ldsm4(uint32_t* r, uint32_t a) {
    asm volatile("ldmatrix.sync.aligned.m8n8.x4.shared.b16 {%0,%1,%2,%3}, [%4];"
                 : "=r"(r[0]), "=r"(r[1]), "=r"(r[2]), "=r"(r[3]) : "r"(a));
}

__device__ __forceinline__ void mma16816(float* d, const uint32_t* a, const uint32_t* b) {
    asm volatile(
        "mma.sync.aligned.m16n8k16.row.col.f32.f16.f16.f32 "
        "{%0,%1,%2,%3}, {%4,%5,%6,%7}, {%8,%9}, {%0,%1,%2,%3};"
        : "+f"(d[0]), "+f"(d[1]), "+f"(d[2]), "+f"(d[3])
        : "r"(a[0]), "r"(a[1]), "r"(a[2]), "r"(a[3]), "r"(b[0]), "r"(b[1]));
}

// ---------------------------------------------------------------------------
// Kernel: per-row rms scale  s[r] = rsqrt(mean(v^2) + eps)
// ---------------------------------------------------------------------------
__global__ void rms_scale_kernel(const float* __restrict__ X, float* __restrict__ out)
{
    const int row = blockIdx.x;
    const int tid = threadIdx.x;
    const float* p = X + (size_t)row * DM;

    float4 v = *(const float4*)(p + tid * 4);
    float s = v.x * v.x + v.y * v.y + v.z * v.z + v.w * v.w;

    __shared__ float red[256];
    red[tid] = s;
    __syncthreads();
    #pragma unroll
    for (int off = 128; off > 0; off >>= 1) {
        if (tid < off) red[tid] += red[tid + off];
        __syncthreads();
    }
    if (tid == 0)
        out[row] = rsqrtf(red[0] * (1.0f / DM) + 1e-6f);
}

// ---------------------------------------------------------------------------
// Kernel: fused scale + fp16 hi/lo split  (row length = DM = 1024)
// ---------------------------------------------------------------------------
__device__ __forceinline__ void split2h(float v, __half& h, __half& l) {
    h = __float2half_rn(v);
    l = __float2half_rn(v - __half2float(h));
}

__global__ __launch_bounds__(256) void scale_split_kernel(
    const float* __restrict__ src, const float* __restrict__ scale,
    __half* __restrict__ hi, __half* __restrict__ lo)
{
    const size_t i = (size_t)blockIdx.x * 256 + threadIdx.x;  // one float4 per thread
    float4 v = ((const float4*)src)[i];
    const float s = scale[i >> 8];   // element row = (4i)>>10 = i>>8
    __half h0, h1, h2, h3, l0, l1, l2, l3;
    split2h(v.x * s, h0, l0); split2h(v.y * s, h1, l1);
    split2h(v.z * s, h2, l2); split2h(v.w * s, h3, l3);
    __half2* H = (__half2*)(hi + 4 * i);
    __half2* L = (__half2*)(lo + 4 * i);
    H[0] = __halves2half2(h0, h1); H[1] = __halves2half2(h2, h3);
    L[0] = __halves2half2(l0, l1); L[1] = __halves2half2(l2, l3);
}

// ---------------------------------------------------------------------------
// Kernel: transpose  W[c,d] -> Wt[d,c]  (raw w, single fp16)
// ---------------------------------------------------------------------------
__global__ void wt_kernel(const float* __restrict__ w, __half* __restrict__ th)
{
    __shared__ float t[32][33];
    const int c = blockIdx.y * 32 + threadIdx.y;
    const int d = blockIdx.x * 32 + threadIdx.x;
    t[threadIdx.y][threadIdx.x] = w[(size_t)c * DM + d];
    __syncthreads();
    const int dd = blockIdx.x * 32 + threadIdx.y;
    const int cc = blockIdx.y * 32 + threadIdx.x;
    th[(size_t)dd * DF + cc] = __float2half_rn(t[threadIdx.x][threadIdx.y]);
}

// ---------------------------------------------------------------------------
// Kernel: row softmax over 4096, emits single fp16 probs
// ---------------------------------------------------------------------------
__global__ __launch_bounds__(256) void softmax_h(const float* __restrict__ S,
                                                 __half* __restrict__ PH)
{
    const int row = blockIdx.x;
    const int tid = threadIdx.x;
    const float* p = S + (size_t)row * DF + tid * 16;

    float v[16];
    #pragma unroll
    for (int j = 0; j < 4; j++) {
        float4 t = *(const float4*)(p + j * 4);
        v[j * 4 + 0] = t.x; v[j * 4 + 1] = t.y;
        v[j * 4 + 2] = t.z; v[j * 4 + 3] = t.w;
    }
    float lm = v[0];
    #pragma unroll
    for (int j = 1; j < 16; j++) lm = fmaxf(lm, v[j]);

    __shared__ float red[256];
    red[tid] = lm;
    __syncthreads();
    #pragma unroll
    for (int off = 128; off > 0; off >>= 1) {
        if (tid < off) red[tid] = fmaxf(red[tid], red[tid + off]);
        __syncthreads();
    }
    const float m = red[0];
    __syncthreads();

    float ls = 0.f;
    #pragma unroll
    for (int j = 0; j < 16; j++) {
        v[j] = __expf(v[j] - m);
        ls += v[j];
    }
    red[tid] = ls;
    __syncthreads();
    #pragma unroll
    for (int off = 128; off > 0; off >>= 1) {
        if (tid < off) red[tid] += red[tid + off];
        __syncthreads();
    }
    const float inv = 1.0f / red[0];

    __half2* ph2 = (__half2*)(PH + (size_t)row * DF + tid * 16);
    #pragma unroll
    for (int j = 0; j < 8; j++) {
        ph2[j] = __halves2half2(__float2half_rn(v[2 * j] * inv),
                                __float2half_rn(v[2 * j + 1] * inv));
    }
}

// ---------------------------------------------------------------------------
// Split-fp16 NT GEMM (3-term) via mma.sync.m16n8k16:
//   C[m,n] = sum_k (Ah+Al)[m,k] * (Bh+Bl)[n,k]   (al*bl dropped)
// BM=128, BN=256, BK=32, 8 warps (2x4), warp tile 64x64, 3-stage cp.async.
// smem rows: 80B pitch (40 halfs), conflict-free non-trans ldmatrix.
// Stage layout: Ah[128x80]=10240 | Al=10240 | Bh[256x80]=20480 | Bl=20480.
// ---------------------------------------------------------------------------
#define STG3   61440
#define GSMEM3 (3 * STG3)    // 184320

__global__ __launch_bounds__(256, 1) void gemm_hsplit(
    const __half* __restrict__ Ah, const __half* __restrict__ Al,
    const __half* __restrict__ Bh, const __half* __restrict__ Bl,
    float* __restrict__ C, int lda, int ldb, int ldc, int KT)
{
    extern __shared__ __align__(16) char smem[];
    const uint32_t sbase = smem_u32_of(smem);
    const int tid  = threadIdx.x;
    const int lane = tid & 31;
    const int wid  = tid >> 5;
    const int wm   = (wid >> 2) * 64;   // 0,64
    const int wn   = (wid & 3) * 64;    // 0,64,128,192
    const int bm   = blockIdx.y * 128;
    const int bn   = blockIdx.x * 256;

    const int lr = tid >> 2;          // 0..63
    const int lc = tid & 3;           // 16B chunk
    const __half* pAh = Ah + (size_t)(bm + lr) * lda + lc * 8;
    const __half* pAl = Al + (size_t)(bm + lr) * lda + lc * 8;
    const __half* pBh = Bh + (size_t)(bn + lr) * ldb + lc * 8;
    const __half* pBl = Bl + (size_t)(bn + lr) * ldb + lc * 8;
    const size_t rstepA = (size_t)64 * lda;
    const size_t rstepB = (size_t)64 * ldb;
    const uint32_t so = lr * 80 + lc * 16;

    float acc[4][8][4];
    #pragma unroll
    for (int i = 0; i < 4; i++)
        #pragma unroll
        for (int j = 0; j < 8; j++)
            #pragma unroll
            for (int k = 0; k < 4; k++) acc[i][j][k] = 0.f;

#define LOAD_ST(kt, slot)                                                     \
    do {                                                                      \
        const int _k0 = (kt) * 32;                                            \
        const uint32_t _sb = sbase + (slot) * STG3 + so;                      \
        cp16(_sb + 0,     pAh + _k0);                                         \
        cp16(_sb + 5120,  pAh + _k0 + rstepA);                                \
        cp16(_sb + 10240, pAl + _k0);                                         \
        cp16(_sb + 15360, pAl + _k0 + rstepA);                                \
        cp16(_sb + 20480, pBh + _k0);                                         \
        cp16(_sb + 25600, pBh + _k0 + rstepB);                                \
        cp16(_sb + 30720, pBh + _k0 + 2 * rstepB);                            \
        cp16(_sb + 35840, pBh + _k0 + 3 * rstepB);                            \
        cp16(_sb + 40960, pBl + _k0);                                         \
        cp16(_sb + 46080, pBl + _k0 + rstepB);                                \
        cp16(_sb + 51200, pBl + _k0 + 2 * rstepB);                            \
        cp16(_sb + 56320, pBl + _k0 + 3 * rstepB);                            \
    } while (0)

    LOAD_ST(0, 0); asm volatile("cp.async.commit_group;" ::: "memory");
    LOAD_ST(1, 1); asm volatile("cp.async.commit_group;" ::: "memory");

    const uint32_t aoff = ((wm + (lane & 15)) * 40 + ((lane >> 4) << 3)) * 2;
    const uint32_t boff = ((wn + (lane & 7) + ((lane >> 4) << 3)) * 40 + (lane & 8)) * 2;

    int slot = 0, nslot = 2;
    for (int kt = 0; kt < KT; ++kt) {
        asm volatile("cp.async.wait_group 1;" ::: "memory");
        __syncthreads();
        const uint32_t sb = sbase + slot * STG3;

        #pragma unroll
        for (int ks = 0; ks < 2; ++ks) {
            const uint32_t kc2 = ks * 32;
            uint32_t ahf[4][4], alf[4][4], bhf[8][2], blf[8][2];
            #pragma unroll
            for (int mt = 0; mt < 4; mt++) {
                ldsm4(ahf[mt], sb + aoff + kc2 + mt * 1280);
                ldsm4(alf[mt], sb + 10240 + aoff + kc2 + mt * 1280);
            }
            #pragma unroll
            for (int g = 0; g < 4; g++) {
                uint32_t r[4];
                ldsm4(r, sb + 20480 + boff + kc2 + g * 1280);
                bhf[g * 2][0] = r[0]; bhf[g * 2][1] = r[1];
                bhf[g * 2 + 1][0] = r[2]; bhf[g * 2 + 1][1] = r[3];
                ldsm4(r, sb + 40960 + boff + kc2 + g * 1280);
                blf[g * 2][0] = r[0]; blf[g * 2][1] = r[1];
                blf[g * 2 + 1][0] = r[2]; blf[g * 2 + 1][1] = r[3];
            }
            #pragma unroll
            for (int mt = 0; mt < 4; mt++)
                #pragma unroll
                for (int nt = 0; nt < 8; nt++) {
                    mma16816(acc[mt][nt], ahf[mt], bhf[nt]);   // hi*hi
                    mma16816(acc[mt][nt], ahf[mt], blf[nt]);   // hi*lo
                    mma16816(acc[mt][nt], alf[mt], bhf[nt]);   // lo*hi
                }
        }
        __syncthreads();
        if (kt + 2 < KT) LOAD_ST(kt + 2, nslot);
        asm volatile("cp.async.commit_group;" ::: "memory");
        slot = (slot == 2) ? 0 : slot + 1;
        nslot = (nslot == 2) ? 0 : nslot + 1;
    }

    #pragma unroll
    for (int mt = 0; mt < 4; mt++) {
        const int row = bm + wm + mt * 16 + (lane >> 2);
        float* r0 = C + (size_t)row * ldc + bn + wn + (lane & 3) * 2;
        float* r1 = r0 + (size_t)8 * ldc;
        #pragma unroll
        for (int nt = 0; nt < 8; nt++) {
            *(float2*)(r0 + nt * 8) = make_float2(acc[mt][nt][0], acc[mt][nt][1]);
            *(float2*)(r1 + nt * 8) = make_float2(acc[mt][nt][2], acc[mt][nt][3]);
        }
    }
#undef LOAD_ST
}

// ---------------------------------------------------------------------------
// Single-fp16 NT GEMM (1 term) — GEMM2 (out = P @ W).
// BM=128, BN=256, warp tile 64x64, 3-stage.
// Stage: A[128x80]=10240 | B[256x80]=20480 -> 30720.
// ---------------------------------------------------------------------------
#define STG1   30720
#define GSMEM1 (3 * STG1)    // 92160

__global__ __launch_bounds__(256, 1) void gemm_h16(
    const __half* __restrict__ A, const __half* __restrict__ B,
    float* __restrict__ C, int lda, int ldb, int ldc, int KT)
{
    extern __shared__ __align__(16) char smem[];
    const uint32_t sbase = smem_u32_of(smem);
    const int tid  = threadIdx.x;
    const int lane = tid & 31;
    const int wid  = tid >> 5;
    const int wm   = (wid >> 2) * 64;
    const int wn   = (wid & 3) * 64;
    const int bm   = blockIdx.y * 128;
    const int bn   = blockIdx.x * 256;

    const int lr = tid >> 2;
    const int lc = tid & 3;
    const __half* pA = A + (size_t)(bm + lr) * lda + lc * 8;
    const __half* pB = B + (size_t)(bn + lr) * ldb + lc * 8;
    const size_t rstepA = (size_t)64 * lda;
    const size_t rstepB = (size_t)64 * ldb;
    const uint32_t so = lr * 80 + lc * 16;

    float acc[4][8][4];
    #pragma unroll
    for (int i = 0; i < 4; i++)
        #pragma unroll
        for (int j = 0; j < 8; j++)
            #pragma unroll
            for (int k = 0; k < 4; k++) acc[i][j][k] = 0.f;

#define LOAD_S1(kt, slot)                                                     \
    do {                                                                      \
        const int _k0 = (kt) * 32;                                            \
        const uint32_t _sb = sbase + (slot) * STG1 + so;                      \
        cp16(_sb + 0,     pA + _k0);                                          \
        cp16(_sb + 5120,  pA + _k0 + rstepA);                                 \
        cp16(_sb + 10240, pB + _k0);                                          \
        cp16(_sb + 15360, pB + _k0 + rstepB);                                 \
        cp16(_sb + 20480, pB + _k0 + 2 * rstepB);                             \
        cp16(_sb + 25600, pB + _k0 + 3 * rstepB);                             \
    } while (0)

    LOAD_S1(0, 0); asm volatile("cp.async.commit_group;" ::: "memory");
    LOAD_S1(1, 1); asm volatile("cp.async.commit_group;" ::: "memory");

    const uint32_t aoff = ((wm + (lane & 15)) * 40 + ((lane >> 4) << 3)) * 2;
    const uint32_t boff = ((wn + (lane & 7) + ((lane >> 4) << 3)) * 40 + (lane & 8)) * 2;

    int slot = 0, nslot = 2;
    for (int kt = 0; kt < KT; ++kt) {
        asm volatile("cp.async.wait_group 1;" ::: "memory");
        __syncthreads();
        const uint32_t sb = sbase + slot * STG1;

        #pragma unroll
        for (int ks = 0; ks < 2; ++ks) {
            const uint32_t kc2 = ks * 32;
            uint32_t af[4][4], bf[8][2];
            #pragma unroll
            for (int mt = 0; mt < 4; mt++)
                ldsm4(af[mt], sb + aoff + kc2 + mt * 1280);
            #pragma unroll
            for (int g = 0; g < 4; g++) {
                uint32_t r[4];
                ldsm4(r, sb + 10240 + boff + kc2 + g * 1280);
                bf[g * 2][0] = r[0]; bf[g * 2][1] = r[1];
                bf[g * 2 + 1][0] = r[2]; bf[g * 2 + 1][1] = r[3];
            }
            #pragma unroll
            for (int mt = 0; mt < 4; mt++)
                #pragma unroll
                for (int nt = 0; nt < 8; nt++)
                    mma16816(acc[mt][nt], af[mt], bf[nt]);
        }
        __syncthreads();
        if (kt + 2 < KT) LOAD_S1(kt + 2, nslot);
        asm volatile("cp.async.commit_group;" ::: "memory");
        slot = (slot == 2) ? 0 : slot + 1;
        nslot = (nslot == 2) ? 0 : nslot + 1;
    }

    #pragma unroll
    for (int mt = 0; mt < 4; mt++) {
        const int row = bm + wm + mt * 16 + (lane >> 2);
        float* r0 = C + (size_t)row * ldc + bn + wn + (lane & 3) * 2;
        float* r1 = r0 + (size_t)8 * ldc;
        #pragma unroll
        for (int nt = 0; nt < 8; nt++) {
            *(float2*)(r0 + nt * 8) = make_float2(acc[mt][nt][0], acc[mt][nt][1]);
            *(float2*)(r1 + nt * 8) = make_float2(acc[mt][nt][2], acc[mt][nt][3]);
        }
    }
#undef LOAD_S1
}

// ---------------------------------------------------------------------------
// Launch
// ---------------------------------------------------------------------------
extern "C" void kernel_launch(void* const* d_in, const int* in_sizes, int n_in,
                              void* d_out, int out_size)
{
    const float* x = (const float*)d_in[0];   // [16384, 1024]
    const float* w = (const float*)d_in[1];   // [4096, 1024]
    float* out = (float*)d_out;               // [16384, 1024]

    float *xscale, *wscale, *scores;
    __half *xhi, *xlo, *whi, *wlo, *wthi, *phi;
    cudaGetSymbolAddress((void**)&xscale, g_xscale);
    cudaGetSymbolAddress((void**)&wscale, g_wscale);
    cudaGetSymbolAddress((void**)&scores, g_scores);
    cudaGetSymbolAddress((void**)&xhi, g_xhi);
    cudaGetSymbolAddress((void**)&xlo, g_xlo);
    cudaGetSymbolAddress((void**)&whi, g_whi);
    cudaGetSymbolAddress((void**)&wlo, g_wlo);
    cudaGetSymbolAddress((void**)&wthi, g_wthi);
    cudaGetSymbolAddress((void**)&phi, g_phi);

    cudaFuncSetAttribute(gemm_hsplit, cudaFuncAttributeMaxDynamicSharedMemorySize,
                         GSMEM3);
    cudaFuncSetAttribute(gemm_h16, cudaFuncAttributeMaxDynamicSharedMemorySize,
                         GSMEM1);

    // Prep: rms scales; scaled fp16 splits; W transpose (fp16)
    rms_scale_kernel<<<MROWS, 256>>>(x, xscale);
    rms_scale_kernel<<<DF,    256>>>(w, wscale);
    scale_split_kernel<<<(MROWS * (DM / 4)) / 256, 256>>>(x, xscale, xhi, xlo);
    scale_split_kernel<<<(DF * (DM / 4)) / 256, 256>>>(w, wscale, whi, wlo);
    {
        dim3 g(DM / 32, DF / 32), b(32, 32);
        wt_kernel<<<g, b>>>(w, wthi);
    }

    // GEMM1 (3-term exact): scores[m,n] = (xs*x)_m . (ws*w)_n
    {
        dim3 g(DF / 256, MROWS / 128);   // 16 x 128
        gemm_hsplit<<<g, 256, GSMEM3>>>(xhi, xlo, whi, wlo, scores,
                                        DM, DM, DF, DM / 32);
    }

    // softmax rows -> fp16 probs
    softmax_h<<<MROWS, 256>>>(scores, phi);

    // GEMM2 (1-term fp16): out[m,d] = sum_c probs[m,c] * w[c,d]
    {
        dim3 g(DM / 256, MROWS / 128);   // 4 x 128
        gemm_h16<<<g, 256, GSMEM1>>>(phi, wthi, out, DF, DF, DM, DF / 32);
    }
}